// round 11
// baseline (speedup 1.0000x reference)
#include <cuda_runtime.h>
#include <math.h>

// EntropyLoss: x [R=65536, C=1024] f32 row-major.
//   n_j  = max( sqrt(sum_i x_ij^2), 1e-12 )
//   out  = -(1/R) * sum_j (1/n_j) * [ sum_i x*ln(x) - ln(n_j) * sum_i x ]
// (eps=1e-8 inside the reference log contributes <1e-6 relative error; dropped)
//
// R11: last point on the reg-budget/MLP curve (the only lever that has moved
// DRAM%): 4 CTAs/SM @ 64-reg budget, fixed-12 front-batched loads (MLP_p1=12).
//   R5: 8/SM, 32 regs, MLP~2  -> 71.3%
//   R6: 5/SM, 48 regs, MLP~8  -> 74.8%   (best, 47.6us)
//   R11: 4/SM, 64 regs, MLP~12 -> ?
// Grid = 148x4 = 592 CTAs, exactly one wave. Tail stays the R10 parallel
// per-tile combine. All scratch re-zeroed each call for graph replay.

#define COLS 1024
#define GRID_X 148          // 148*4 = 592 CTAs = 4/SM, one wave
#define GRID_Y 4            // column tiles of 256
#define LN2 0.6931471805599453f

__device__ float g_part[3][COLS];      // [0]=sum x^2, [1]=sum x, [2]=sum x*log2(x)
__device__ float g_tile[GRID_Y];       // per-tile partial of the final sum
__device__ unsigned int g_tile_count[GRID_Y];
__device__ unsigned int g_final;

__global__ __launch_bounds__(256, 4) void el_fused_kernel(const float* __restrict__ x,
                                                          float* __restrict__ out,
                                                          int rows) {
    const int tid     = threadIdx.x;
    const int cg      = tid & 63;     // 64 float4 column-groups per block (256 cols)
    const int slice   = tid >> 6;     // 4 row slices per block
    const int ty      = blockIdx.y;
    const int colbase = ty * 256;
    const int g4      = (colbase >> 2) + cg;   // float4 index within a row

    const float4* __restrict__ p = (const float4*)x;

    float s2[4] = {0.f, 0.f, 0.f, 0.f};
    float s1[4] = {0.f, 0.f, 0.f, 0.f};
    float sx[4] = {0.f, 0.f, 0.f, 0.f};

    const int  rstride = GRID_X * 4;                 // 592 row slices total
    const int  r0      = blockIdx.x * 4 + slice;
    const long step    = (long)rstride * (COLS / 4);
    const float4* __restrict__ q = p + (long)r0 * (COLS / 4) + g4;

    const int iters = (rows - r0 + rstride - 1) / rstride;   // ~110-111
    const int itU   = iters - (iters % 12);

    for (int b = 0; b < itU; b += 12) {
        // fixed trip count of 12: fully unrolled, 12 independent front-batched
        // float4 loads (48 data regs fit the 64-reg budget at 4 CTAs/SM)
        #pragma unroll
        for (int u = 0; u < 12; u++) {
            float4 v = q[(long)u * step];
            float vv[4] = {v.x, v.y, v.z, v.w};
            #pragma unroll
            for (int k = 0; k < 4; k++) {
                float a = vv[k];
                s2[k] = fmaf(a, a, s2[k]);
                s1[k] += a;
                // x*log2(x): at a==0 this is fmaf(0, lg2(1e-37), s) == s
                float l = __log2f(fmaxf(a, 1e-37f));
                sx[k] = fmaf(a, l, sx[k]);
            }
        }
        q += 12 * step;
    }
    for (int i = itU; i < iters; i++) {
        float4 v = *q;
        q += step;
        float vv[4] = {v.x, v.y, v.z, v.w};
        #pragma unroll
        for (int k = 0; k < 4; k++) {
            float a = vv[k];
            s2[k] = fmaf(a, a, s2[k]);
            s1[k] += a;
            float l = __log2f(fmaxf(a, 1e-37f));
            sx[k] = fmaf(a, l, sx[k]);
        }
    }

    // Reduce the 4 row-slices within the block before touching L2 atomics.
    __shared__ float red[4][64 * 12];
    #pragma unroll
    for (int k = 0; k < 4; k++) {
        red[slice][cg * 12 + 0 + k] = s2[k];
        red[slice][cg * 12 + 4 + k] = s1[k];
        red[slice][cg * 12 + 8 + k] = sx[k];
    }
    __syncthreads();

    for (int i = tid; i < 64 * 12; i += 256) {
        float t = red[0][i] + red[1][i] + red[2][i] + red[3][i];
        int cg2  = i / 12;
        int comp = i % 12;
        int type = comp >> 2;     // 0: x^2, 1: x, 2: x*log2(x)
        int sub  = comp & 3;
        int col  = colbase + cg2 * 4 + sub;
        atomicAdd(&g_part[type][col], t);
    }

    // ---- per-tile last block: combine this tile's 256 columns ----
    __shared__ int amTileLast;
    __threadfence();
    __syncthreads();
    if (tid == 0) {
        unsigned v = atomicAdd(&g_tile_count[ty], 1u);
        amTileLast = (v == GRID_X - 1);
    }
    __syncthreads();
    if (!amTileLast) return;

    {
        const int j = colbase + tid;   // each thread owns one column of the tile
        float S2 = __ldcg(&g_part[0][j]);
        float S1 = __ldcg(&g_part[1][j]);
        float SX = __ldcg(&g_part[2][j]);
        float n  = fmaxf(sqrtf(S2), 1e-12f);
        float t  = (SX * LN2 - S1 * logf(n)) / n;

        // re-zero this tile's scratch for the next graph replay
        g_part[0][j] = 0.0f;
        g_part[1][j] = 0.0f;
        g_part[2][j] = 0.0f;
        if (tid == 0) g_tile_count[ty] = 0u;

        __shared__ float sm[256];
        sm[tid] = t;
        __syncthreads();
        #pragma unroll
        for (int s = 128; s > 0; s >>= 1) {
            if (tid < s) sm[tid] += sm[tid + s];
            __syncthreads();
        }
        if (tid == 0) g_tile[ty] = sm[0];
    }

    // ---- global last tile writes the output ----
    __shared__ int amFinal;
    __threadfence();
    __syncthreads();
    if (tid == 0) {
        unsigned v = atomicAdd(&g_final, 1u);
        amFinal = (v == GRID_Y - 1);
    }
    __syncthreads();
    if (!amFinal) return;

    if (tid == 0) {
        float s = 0.f;
        #pragma unroll
        for (int m = 0; m < GRID_Y; m++) s += __ldcg(&g_tile[m]);
        out[0] = -s / (float)rows;
        g_final = 0u;
    }
}

extern "C" void kernel_launch(void* const* d_in, const int* in_sizes, int n_in,
                              void* d_out, int out_size) {
    const float* x = (const float*)d_in[0];
    int rows = in_sizes[0] / COLS;   // 65536
    dim3 grid(GRID_X, GRID_Y);
    el_fused_kernel<<<grid, 256>>>(x, (float*)d_out, rows);
}

// round 12
// speedup vs baseline: 1.0795x; 1.0795x over previous
#include <cuda_runtime.h>
#include <math.h>

// EntropyLoss: x [R=65536, C=1024] f32 row-major.
//   n_j  = max( sqrt(sum_i x_ij^2), 1e-12 )
//   out  = -(1/R) * sum_j (1/n_j) * [ sum_i x*ln(x) - ln(n_j) * sum_i x ]
// (eps=1e-8 inside the reference log contributes <1e-6 relative error; dropped)
//
// R12: the untested corner of the occupancy x MLP matrix. 512-thread CTAs at
// 2 CTAs/SM: 64-reg budget (unroll-8 needs ~54 -> NO spill, unlike R11's
// unroll-12 @ 64) with 64 warps/SM AND 8 front-batched loads per warp.
//   R5:  64w, MLP~2 (32r)          -> 71.3%
//   R6:  40w, MLP~8 (48r)          -> 74.8%  (best, 47.6us)
//   R11: 32w, MLP12 (64r, SPILLED) -> 66.8%
//   R12: 64w, MLP~8 (64r, fits)    -> ?
// Grid = 74x4 = 296 CTAs, exactly one wave. Parallel per-tile tail (R10).
// All scratch re-zeroed each call for graph replay.

#define COLS 1024
#define GRID_X 74           // 74*4 = 296 CTAs = 2/SM, one wave
#define GRID_Y 4            // column tiles of 256
#define NSLICE 8            // row slices per block (512 threads / 64 col-groups)
#define LN2 0.6931471805599453f

__device__ float g_part[3][COLS];      // [0]=sum x^2, [1]=sum x, [2]=sum x*log2(x)
__device__ float g_tile[GRID_Y];       // per-tile partial of the final sum
__device__ unsigned int g_tile_count[GRID_Y];
__device__ unsigned int g_final;

__global__ __launch_bounds__(512, 2) void el_fused_kernel(const float* __restrict__ x,
                                                          float* __restrict__ out,
                                                          int rows) {
    const int tid     = threadIdx.x;
    const int cg      = tid & 63;     // 64 float4 column-groups per block (256 cols)
    const int slice   = tid >> 6;     // 8 row slices per block
    const int ty      = blockIdx.y;
    const int colbase = ty * 256;
    const int g4      = (colbase >> 2) + cg;   // float4 index within a row

    const float4* __restrict__ p = (const float4*)x;

    float s2[4] = {0.f, 0.f, 0.f, 0.f};
    float s1[4] = {0.f, 0.f, 0.f, 0.f};
    float sx[4] = {0.f, 0.f, 0.f, 0.f};

    const int  rstride = GRID_X * NSLICE;            // 592 row slices total
    const int  r0      = blockIdx.x * NSLICE + slice;
    const long step    = (long)rstride * (COLS / 4);
    const float4* __restrict__ q = p + (long)r0 * (COLS / 4) + g4;

    const int iters = (rows - r0 + rstride - 1) / rstride;   // ~110-111
    const int it8   = iters & ~7;

    for (int b = 0; b < it8; b += 8) {
        // fixed trip count of 8: fully unrolled, 8 independent front-batched
        // float4 loads (32 data regs + 12 acc fit the 64-reg budget cleanly)
        #pragma unroll
        for (int u = 0; u < 8; u++) {
            float4 v = q[(long)u * step];
            float vv[4] = {v.x, v.y, v.z, v.w};
            #pragma unroll
            for (int k = 0; k < 4; k++) {
                float a = vv[k];
                s2[k] = fmaf(a, a, s2[k]);
                s1[k] += a;
                // x*log2(x): at a==0 this is fmaf(0, lg2(1e-37), s) == s
                float l = __log2f(fmaxf(a, 1e-37f));
                sx[k] = fmaf(a, l, sx[k]);
            }
        }
        q += 8 * step;
    }
    for (int i = it8; i < iters; i++) {
        float4 v = *q;
        q += step;
        float vv[4] = {v.x, v.y, v.z, v.w};
        #pragma unroll
        for (int k = 0; k < 4; k++) {
            float a = vv[k];
            s2[k] = fmaf(a, a, s2[k]);
            s1[k] += a;
            float l = __log2f(fmaxf(a, 1e-37f));
            sx[k] = fmaf(a, l, sx[k]);
        }
    }

    // Reduce the 8 row-slices within the block before touching L2 atomics.
    __shared__ float red[NSLICE][64 * 12];
    #pragma unroll
    for (int k = 0; k < 4; k++) {
        red[slice][cg * 12 + 0 + k] = s2[k];
        red[slice][cg * 12 + 4 + k] = s1[k];
        red[slice][cg * 12 + 8 + k] = sx[k];
    }
    __syncthreads();

    for (int i = tid; i < 64 * 12; i += 512) {
        float t = red[0][i] + red[1][i] + red[2][i] + red[3][i]
                + red[4][i] + red[5][i] + red[6][i] + red[7][i];
        int cg2  = i / 12;
        int comp = i % 12;
        int type = comp >> 2;     // 0: x^2, 1: x, 2: x*log2(x)
        int sub  = comp & 3;
        int col  = colbase + cg2 * 4 + sub;
        atomicAdd(&g_part[type][col], t);
    }

    // ---- per-tile last block: combine this tile's 256 columns ----
    __shared__ int amTileLast;
    __threadfence();
    __syncthreads();
    if (tid == 0) {
        unsigned v = atomicAdd(&g_tile_count[ty], 1u);
        amTileLast = (v == GRID_X - 1);
    }
    __syncthreads();
    if (!amTileLast) return;

    __shared__ float sm[256];
    if (tid < 256) {
        const int j = colbase + tid;   // each of 256 threads owns one column
        float S2 = __ldcg(&g_part[0][j]);
        float S1 = __ldcg(&g_part[1][j]);
        float SX = __ldcg(&g_part[2][j]);
        float n  = fmaxf(sqrtf(S2), 1e-12f);
        sm[tid]  = (SX * LN2 - S1 * logf(n)) / n;

        // re-zero this tile's scratch for the next graph replay
        g_part[0][j] = 0.0f;
        g_part[1][j] = 0.0f;
        g_part[2][j] = 0.0f;
    }
    if (tid == 0) g_tile_count[ty] = 0u;
    __syncthreads();
    #pragma unroll
    for (int s = 128; s > 0; s >>= 1) {
        if (tid < s) sm[tid] += sm[tid + s];
        __syncthreads();
    }
    if (tid == 0) g_tile[ty] = sm[0];

    // ---- global last tile writes the output ----
    __shared__ int amFinal;
    __threadfence();
    __syncthreads();
    if (tid == 0) {
        unsigned v = atomicAdd(&g_final, 1u);
        amFinal = (v == GRID_Y - 1);
    }
    __syncthreads();
    if (!amFinal) return;

    if (tid == 0) {
        float s = 0.f;
        #pragma unroll
        for (int m = 0; m < GRID_Y; m++) s += __ldcg(&g_tile[m]);
        out[0] = -s / (float)rows;
        g_final = 0u;
    }
}

extern "C" void kernel_launch(void* const* d_in, const int* in_sizes, int n_in,
                              void* d_out, int out_size) {
    const float* x = (const float*)d_in[0];
    int rows = in_sizes[0] / COLS;   // 65536
    dim3 grid(GRID_X, GRID_Y);
    el_fused_kernel<<<grid, 512>>>(x, (float*)d_out, rows);
}